// round 17
// baseline (speedup 1.0000x reference)
#include <cuda_runtime.h>

// HopfieldNetwork: B=8, N=4096, ITERS=10 asynchronous sweeps.
// R17 = R16 (1240us) micro-opts:
//  (1) spec-row loads made UNCONDITIONAL (row index clamped to 0 when there
//      is no 2nd/3rd candidate; spec_id kept at -1 so it never matches) --
//      removes two uniform branch regions (BSSY/BSYNC ~35cyc each) from the
//      per-flip round.
//  (2) r2/r3 decode + spec LDGs issued BEFORE the axpy, maximizing load
//      latency headroom before next-round consumption.
// Everything else identical to R16: one barrier per flip, static per-sweep
// keys, two register spec rows, fused quantize+gemv init.
// z int64 scale 2^40; wq = rn(W*2^40); flip delta = +-2*wq via IMAD.WIDE.

constexpr int NN  = 4096;
constexpr int TPB = 512;
constexpr int ZPT = 8;
constexpr int INF = 0x7FFFFFFF;

__device__ long long g_z[8 * NN];                      // z, int64, scale 2^40
__device__ __align__(16) int g_Wq[NN * NN];            // rn(W * 2^40)
__device__ __align__(16) unsigned char g_xsign[NN];    // bit b = (x[b][c] < 0)

// ---------------------------------------------------------------------------
// Kernel 0: pack x signs (one byte per column).
// ---------------------------------------------------------------------------
__global__ void pack_x(const float* __restrict__ x, int B)
{
    const int c = blockIdx.x * 256 + threadIdx.x;
    unsigned v = 0;
#pragma unroll
    for (int b = 0; b < 8; b++)
        if (b < B && x[(size_t)b * NN + c] < 0.f) v |= 1u << b;
    g_xsign[c] = (unsigned char)v;
}

// ---------------------------------------------------------------------------
// Kernel 1 (fused): quantize one W row, store g_Wq, and compute
// z0[b][row] = sum_c wq[row][c]*y[b][c] in the same pass. One block per row.
// ---------------------------------------------------------------------------
__global__ void __launch_bounds__(256) gemv_prep(const float* __restrict__ W,
                                                 int B)
{
    const int row  = blockIdx.x;
    const int tid  = threadIdx.x;
    const int base = tid * 16;
    const int lane = tid & 31, wid = tid >> 5;

    const float4* w4 = reinterpret_cast<const float4*>(W + (size_t)row * NN + base);
    int wq[16];
#pragma unroll
    for (int g = 0; g < 4; g++) {
        const float4 v = w4[g];
        wq[4 * g + 0] = __float2int_rn(v.x * 0x1.0p40f);
        wq[4 * g + 1] = __float2int_rn(v.y * 0x1.0p40f);
        wq[4 * g + 2] = __float2int_rn(v.z * 0x1.0p40f);
        wq[4 * g + 3] = __float2int_rn(v.w * 0x1.0p40f);
    }
    int4* o4 = reinterpret_cast<int4*>(g_Wq + (size_t)row * NN + base);
#pragma unroll
    for (int g = 0; g < 4; g++)
        o4[g] = make_int4(wq[4 * g + 0], wq[4 * g + 1], wq[4 * g + 2], wq[4 * g + 3]);

    const uint4 sb4 = *reinterpret_cast<const uint4*>(g_xsign + base);
    const unsigned sb[4] = {sb4.x, sb4.y, sb4.z, sb4.w};

    long long acc[8];
#pragma unroll
    for (int b = 0; b < 8; b++) acc[b] = 0ll;

#pragma unroll
    for (int k = 0; k < 16; k++) {
        const unsigned byte = (sb[k >> 2] >> (8 * (k & 3))) & 0xFFu;
        const int w = wq[k];
#pragma unroll
        for (int b = 0; b < 8; b++) {
            const int yb = 1 - 2 * (int)((byte >> b) & 1u);
            acc[b] += (long long)w * yb;          // IMAD.WIDE
        }
    }

#pragma unroll
    for (int b = 0; b < 8; b++) {
#pragma unroll
        for (int off = 16; off > 0; off >>= 1)
            acc[b] += __shfl_down_sync(0xffffffffu, acc[b], off);
    }
    __shared__ long long red[8][8];
    if (lane == 0) {
#pragma unroll
        for (int b = 0; b < 8; b++) red[wid][b] = acc[b];
    }
    __syncthreads();
    if (tid < 8) {
        long long s = 0ll;
#pragma unroll
        for (int w2 = 0; w2 < 8; w2++) s += red[w2][tid];
        if (tid < B) g_z[tid * NN + row] = s;
    }
}

// ---------------------------------------------------------------------------
// Kernel 2: one block per sample, one barrier per flip.
// Key pack: bits[0]=nb(=!y_sign), [1:13]=neuron i, [13:25]=pos-in-sweep.
// ---------------------------------------------------------------------------
__global__ void __launch_bounds__(TPB, 1) hopfield_seq(
    const float* __restrict__ x,
    const int*   __restrict__ perms,
    float*       __restrict__ out,
    int iters)
{
    const int b    = blockIdx.x;
    const int tid  = threadIdx.x;
    const int lane = tid & 31;
    const int wid  = tid >> 5;          // 16 warps
    const int base = tid * ZPT;

    __shared__ __align__(16) unsigned short pos_of[NN];   // neuron -> pos
    __shared__ __align__(16) int sh_slot[2][32];          // upper 16 = INF pad

    if (tid < 32) { sh_slot[0][tid] = INF; sh_slot[1][tid] = INF; }

    // ---- load z slice and x signs into registers ----
    long long z[ZPT];
    {
        const long long* gz = g_z + (size_t)b * NN + base;
#pragma unroll
        for (int k = 0; k < ZPT; k++) z[k] = gz[k];
    }

    unsigned ym = 0;   // bit k = (y[base+k] < 0)
    {
        const float4* x4 = reinterpret_cast<const float4*>(x + (size_t)b * NN + base);
#pragma unroll
        for (int g = 0; g < 2; g++) {
            const float4 xv = x4[g];
            ym |= (__float_as_uint(xv.x) >> 31) << (4 * g + 0);
            ym |= (__float_as_uint(xv.y) >> 31) << (4 * g + 1);
            ym |= (__float_as_uint(xv.z) >> 31) << (4 * g + 2);
            ym |= (__float_as_uint(xv.w) >> 31) << (4 * g + 3);
        }
    }

    const int* pb = perms + (size_t)b * iters * NN;
    int parity   = 0;
    int spec_id  = -1, spec_id2 = -1;    // neurons held in specv / specv2
    int specv[ZPT], specv2[ZPT];
#pragma unroll
    for (int k = 0; k < ZPT; k++) { specv[k] = 0; specv2[k] = 0; }

    for (int sweep = 0; sweep < iters; sweep++) {
        // ---- build neuron -> position table for this sweep ----
        const int* ps = pb + sweep * NN;
        {
            const int4* p4 = reinterpret_cast<const int4*>(ps + tid * 8);
#pragma unroll
            for (int g = 0; g < 2; g++) {
                const int4 a = p4[g];
                const int p0 = tid * 8 + g * 4;
                pos_of[a.x] = (unsigned short)(p0 + 0);
                pos_of[a.y] = (unsigned short)(p0 + 1);
                pos_of[a.z] = (unsigned short)(p0 + 2);
                pos_of[a.w] = (unsigned short)(p0 + 3);
            }
        }
        __syncthreads();                         // pos_of visible

        // ---- static per-sweep candidate keys + sign-xor masks ----
        int ckey[ZPT];      // (pos<<13)|(neuron<<1)|(!y_sign)
        int zmask[ZPT];     // y_sign << 31
#pragma unroll
        for (int k = 0; k < ZPT; k++) {
            const int yb = (int)((ym >> k) & 1u);
            ckey[k]  = ((int)pos_of[base + k] << 13) | ((base + k) << 1) | (yb ^ 1);
            zmask[k] = yb << 31;
        }

        int thr = -1;

        // ---- initial candidates for this sweep ----
        {
            unsigned key = (unsigned)INF;
#pragma unroll
            for (int k = 0; k < ZPT; k++) {
                const int t = (int)(z[k] >> 32) ^ zmask[k];
                if (t < 0) key = min(key, (unsigned)ckey[k]);
            }
            const unsigned wmin = __reduce_min_sync(0xffffffffu, key);
            if (lane == 0) sh_slot[parity][wid] = (int)wmin;
        }
        __syncthreads();                         // slots visible

        // ---- flip rounds: one barrier each ----
        for (;;) {
            // lane-parallel decode: one slot per lane (padded), redux top-3
            const int a  = sh_slot[parity][lane];
            parity ^= 1;
            const int mk = (int)__reduce_min_sync(0xffffffffu, (unsigned)a);
            if (mk == INF) break;                // sweep finished

            const int fi = (mk >> 1) & 0xFFF;
            const int nb = mk & 1;
            thr = mk;
            const int sfd = 2 - 4 * nb;          // flip delta = +-2*wq

            // ---- next-round speculation FIRST: issue spec LDGs early ----
            const int e  = (a == mk) ? INF : a;
            const int r2 = (int)__reduce_min_sync(0xffffffffu, (unsigned)e);
            const int e3 = (e == r2) ? INF : e;
            const int r3 = (int)__reduce_min_sync(0xffffffffu, (unsigned)e3);

            const int n1 = (r2 != INF) ? ((r2 >> 1) & 0xFFF) : -1;
            const int n2 = (r3 != INF) ? ((r3 >> 1) & 0xFFF) : -1;
            const int l1 = (n1 >= 0) ? n1 : 0;   // clamped: unconditional load
            const int l2 = (n2 >= 0) ? n2 : 0;

            const int4* s4a =
                reinterpret_cast<const int4*>(g_Wq + (size_t)l1 * NN + base);
            const int4 sa0 = __ldg(s4a + 0), sa1 = __ldg(s4a + 1);
            const int4* s4b =
                reinterpret_cast<const int4*>(g_Wq + (size_t)l2 * NN + base);
            const int4 sb0 = __ldg(s4b + 0), sb1 = __ldg(s4b + 1);

            // ---- axpy: one IMAD.WIDE per element (register rows preferred) ----
            if (fi == spec_id) {                 // uniform: primary spec hit
#pragma unroll
                for (int k = 0; k < ZPT; k++)
                    z[k] += (long long)specv[k] * sfd;
            } else if (fi == spec_id2) {         // uniform: secondary spec hit
#pragma unroll
                for (int k = 0; k < ZPT; k++)
                    z[k] += (long long)specv2[k] * sfd;
            } else {                             // miss: demand load
                const int4* w4 =
                    reinterpret_cast<const int4*>(g_Wq + (size_t)fi * NN + base);
                const int4 da = __ldg(w4 + 0), db = __ldg(w4 + 1);
                const int dv[ZPT] = {da.x, da.y, da.z, da.w,
                                     db.x, db.y, db.z, db.w};
#pragma unroll
                for (int k = 0; k < ZPT; k++)
                    z[k] += (long long)dv[k] * sfd;
            }

            // commit spec registers for next round
            specv[0] = sa0.x;  specv[1] = sa0.y;  specv[2] = sa0.z;  specv[3] = sa0.w;
            specv[4] = sa1.x;  specv[5] = sa1.y;  specv[6] = sa1.z;  specv[7] = sa1.w;
            specv2[0] = sb0.x; specv2[1] = sb0.y; specv2[2] = sb0.z; specv2[3] = sb0.w;
            specv2[4] = sb1.x; specv2[5] = sb1.y; specv2[6] = sb1.z; specv2[7] = sb1.w;
            spec_id  = n1;
            spec_id2 = n2;

            // owner records the flip (stale ckey/zmask excluded by ckey > thr)
            if (tid == (fi >> 3)) ym ^= 1u << (fi & 7);

            // ---- candidate regeneration: static keys, sign-xor test ----
            {
                unsigned k0 = (unsigned)INF, k1 = (unsigned)INF;
#pragma unroll
                for (int k = 0; k < ZPT; k += 2) {
                    const int t0 = (int)(z[k] >> 32) ^ zmask[k];
                    const int t1 = (int)(z[k + 1] >> 32) ^ zmask[k + 1];
                    if (t0 < 0 && ckey[k] > thr)     k0 = min(k0, (unsigned)ckey[k]);
                    if (t1 < 0 && ckey[k + 1] > thr) k1 = min(k1, (unsigned)ckey[k + 1]);
                }
                const unsigned wmin =
                    __reduce_min_sync(0xffffffffu, min(k0, k1));
                if (lane == 0) sh_slot[parity][wid] = (int)wmin;
            }
            __syncthreads();                     // the single barrier
        }
    }

    // ---- write y from register state ----
    float4* o4 = reinterpret_cast<float4*>(out + (size_t)b * NN + base);
#pragma unroll
    for (int g = 0; g < 2; g++) {
        float4 o;
        o.x = ((ym >> (4 * g + 0)) & 1u) ? -1.0f : 1.0f;
        o.y = ((ym >> (4 * g + 1)) & 1u) ? -1.0f : 1.0f;
        o.z = ((ym >> (4 * g + 2)) & 1u) ? -1.0f : 1.0f;
        o.w = ((ym >> (4 * g + 3)) & 1u) ? -1.0f : 1.0f;
        o4[g] = o;
    }
}

// ---------------------------------------------------------------------------
extern "C" void kernel_launch(void* const* d_in, const int* in_sizes, int n_in,
                              void* d_out, int out_size)
{
    const float* x     = (const float*)d_in[0];
    const float* W     = (const float*)d_in[1];
    const int*   perms = (const int*)  d_in[2];
    float*       out   = (float*)d_out;

    const int B     = in_sizes[0] / NN;
    const int iters = in_sizes[2] / in_sizes[0];

    pack_x<<<NN / 256, 256>>>(x, B);
    gemv_prep<<<NN, 256>>>(W, B);
    hopfield_seq<<<B, TPB>>>(x, perms, out, iters);
}